// round 1
// baseline (speedup 1.0000x reference)
#include <cuda_runtime.h>

// Problem constants
#define BSZ    128
#define NRAYS  131072          // B*H*W = 2*256*256
#define NBLK   (NRAYS / BSZ)   // 1024
#define HW     65536
#define C_OFF  0
#define F_OFF  393216          // B*3*HW
#define D_OFF  786432          // 2*B*3*HW

__device__ float g_rayd[NRAYS];
__device__ float g_pmin[NBLK];
__device__ float g_pmax[NBLK];
__device__ float g_mm[2];

__device__ __forceinline__ float sigm(float x) {
    // sigmoid via fast ex2 + fast reciprocal (each ~2 ulp; clamped usage downstream)
    return __fdividef(1.0f, 1.0f + __expf(-x));
}

__global__ void __launch_bounds__(BSZ) nerf_main(
    const float* __restrict__ tm,   // transform_matrix (2,3,4)
    const float* __restrict__ Wq,   // W_query (6,4)
    float* __restrict__ out)
{
    __shared__ float sfd[64 * BSZ];   // fine depths, [sample][tid], conflict-free
    const int tid = threadIdx.x;
    const int r  = blockIdx.x * BSZ + tid;
    const int b  = r >> 16;          // r / HW
    const int n  = r & 65535;        // ray index within batch
    const int pi = n >> 8;           // row i  -> y
    const int pj = n & 255;          // col j  -> x

    // camera dirs: linspace(1,-1,256); endpoint exact
    float xv = 1.0f - (float)pj * (2.0f / 255.0f); if (pj == 255) xv = -1.0f;
    float yv = 1.0f - (float)pi * (2.0f / 255.0f); if (pi == 255) yv = -1.0f;
    float cx = xv / 4.2f;
    float cy = yv / 4.2f;

    const float* M = tm + b * 12;
    float ddx = M[0]*cx + M[1]*cy + M[2];
    float ddy = M[4]*cx + M[5]*cy + M[6];
    float ddz = M[8]*cx + M[9]*cy + M[10];
    float ox = M[3], oy = M[7], oz = M[11];

    // feat(d) = base + d*slope   (query MLP is linear in depth along a ray)
    float base[4], slope[4];
    #pragma unroll
    for (int c = 0; c < 4; c++) {
        float w0 = Wq[c], w1 = Wq[4+c], w2 = Wq[8+c];
        float w3 = Wq[12+c], w4 = Wq[16+c], w5 = Wq[20+c];
        slope[c] = ddx*w0 + ddy*w1 + ddz*w2;
        base[c]  = ox*w0 + oy*w1 + oz*w2 + ddx*w3 + ddy*w4 + ddz*w5;
    }

    const float STEP = 1.9f / 63.0f;

    // ---- Pass 1: coarse ray march (accumulate color + weight sum) ----
    float T = 1.0f, a0 = 0.f, a1 = 0.f, a2 = 0.f, s = 0.f;
    #pragma unroll 4
    for (int p = 0; p < 64; p++) {
        float d  = (p == 63) ? 2.0f : fmaf((float)p, STEP, 0.1f);
        float op = sigm(fmaf(d, slope[0], base[0]));
        float w  = op * T;
        T *= (1.0f - op);
        a0 = fmaf(w, sigm(fmaf(d, slope[1], base[1])), a0);
        a1 = fmaf(w, sigm(fmaf(d, slope[2], base[2])), a1);
        a2 = fmaf(w, sigm(fmaf(d, slope[3], base[3])), a2);
        s += w;
    }
    s += 64.0f * 1e-5f;   // total of wpad = w + 1e-5

    // ---- Pass 2: fused unnormalized-CDF walk + inverse-CDF sampling ----
    // searchsorted(cumsum(wpad)/s, u, 'right')  ==  searchsorted(cumsum(wpad), u*s)
    // u sorted & cdf sorted -> single streaming 2-pointer pass, no cdf array.
    {
        float T2 = 1.0f, cprev = 0.0f, prevbin = 0.0f, dprev = 0.1f;
        int k = 0;
        for (int p = 0; p < 64; p++) {
            float d  = (p == 63) ? 2.0f : fmaf((float)p, STEP, 0.1f);
            float op = sigm(fmaf(d, slope[0], base[0]));
            float w  = op * T2;
            T2 *= (1.0f - op);
            float cc = cprev + w + 1e-5f;
            while (k <= 64) {
                float u = (float)k * (1.0f / 64.0f);
                if (!(u * s < cc)) break;      // ind == p  (side='right')
                float bin;
                if (p == 0) {
                    bin = 0.1f;                // below==above==0 -> depth[0]
                } else {
                    float t = __fdividef(fmaf(u, s, -cprev), cc - cprev);
                    t = fminf(fmaxf(t, 0.0f), 1.0f);
                    bin = fmaf(t, d - dprev, dprev);
                }
                if (k > 0) sfd[(k - 1) * BSZ + tid] = 0.5f * (prevbin + bin);
                prevbin = bin;
                k++;
            }
            cprev = cc;
            dprev = d;
        }
        while (k <= 64) {                      // ind == 64 -> depth[63] = FAR
            float bin = 2.0f;
            if (k > 0) sfd[(k - 1) * BSZ + tid] = 0.5f * (prevbin + bin);
            prevbin = bin;
            k++;
        }
    }

    // ---- Pass 3: merged (coarse ∪ fine) march via 2-pointer merge ----
    float T3 = 1.0f, f0 = 0.f, f1 = 0.f, f2 = 0.f, fop = 0.f, accd = 0.f;
    int pc = 0, pf = 0;
    #pragma unroll 2
    for (int m = 0; m < 128; m++) {
        float dc = (pc < 64) ? ((pc == 63) ? 2.0f : fmaf((float)pc, STEP, 0.1f)) : 3.0e38f;
        float df = (pf < 64) ? sfd[pf * BSZ + tid] : 3.0e38f;
        float d;
        if (dc <= df) { d = dc; pc++; } else { d = df; pf++; }
        float op = sigm(fmaf(d, slope[0], base[0]));
        float w  = op * T3;
        T3 *= (1.0f - op);
        f0 = fmaf(w, sigm(fmaf(d, slope[1], base[1])), f0);
        f1 = fmaf(w, sigm(fmaf(d, slope[2], base[2])), f1);
        f2 = fmaf(w, sigm(fmaf(d, slope[3], base[3])), f2);
        fop += w;
        accd = fmaf(w, d, accd);
    }
    fop = fminf(fop, 1.0f);
    float rayd = accd + (1.0f - fop) * 2.0f;   // d_all.max() == FAR globally

    // ---- Outputs ----
    out[C_OFF + (3*b + 0) * HW + n] = a0;
    out[C_OFF + (3*b + 1) * HW + n] = a1;
    out[C_OFF + (3*b + 2) * HW + n] = a2;
    out[F_OFF + (3*b + 0) * HW + n] = f0;
    out[F_OFF + (3*b + 1) * HW + n] = f1;
    out[F_OFF + (3*b + 2) * HW + n] = f2;
    g_rayd[r] = rayd;

    // ---- block-level min/max partials ----
    float mn = rayd, mx = rayd;
    #pragma unroll
    for (int o = 16; o; o >>= 1) {
        mn = fminf(mn, __shfl_xor_sync(0xffffffffu, mn, o));
        mx = fmaxf(mx, __shfl_xor_sync(0xffffffffu, mx, o));
    }
    __shared__ float smn[BSZ / 32], smx[BSZ / 32];
    if ((tid & 31) == 0) { smn[tid >> 5] = mn; smx[tid >> 5] = mx; }
    __syncthreads();
    if (tid == 0) {
        #pragma unroll
        for (int w = 1; w < BSZ / 32; w++) {
            mn = fminf(mn, smn[w]);
            mx = fmaxf(mx, smx[w]);
        }
        g_pmin[blockIdx.x] = mn;
        g_pmax[blockIdx.x] = mx;
    }
}

__global__ void __launch_bounds__(1024) nerf_reduce()
{
    const int t = threadIdx.x;
    float mn = g_pmin[t];
    float mx = g_pmax[t];
    #pragma unroll
    for (int o = 16; o; o >>= 1) {
        mn = fminf(mn, __shfl_xor_sync(0xffffffffu, mn, o));
        mx = fmaxf(mx, __shfl_xor_sync(0xffffffffu, mx, o));
    }
    __shared__ float smn[32], smx[32];
    if ((t & 31) == 0) { smn[t >> 5] = mn; smx[t >> 5] = mx; }
    __syncthreads();
    if (t < 32) {
        mn = smn[t];
        mx = smx[t];
        #pragma unroll
        for (int o = 16; o; o >>= 1) {
            mn = fminf(mn, __shfl_xor_sync(0xffffffffu, mn, o));
            mx = fmaxf(mx, __shfl_xor_sync(0xffffffffu, mx, o));
        }
        if (t == 0) { g_mm[0] = mn; g_mm[1] = mx; }
    }
}

__global__ void __launch_bounds__(256) nerf_norm(float* __restrict__ out)
{
    const int r = blockIdx.x * 256 + threadIdx.x;
    const float mn = g_mm[0];
    const float mx = g_mm[1];
    out[D_OFF + r] = (g_rayd[r] - mn) / (mx - mn);
}

extern "C" void kernel_launch(void* const* d_in, const int* in_sizes, int n_in,
                              void* d_out, int out_size)
{
    const float* tm = (const float*)d_in[0];   // transform_matrix (2,3,4)
    const float* Wq = (const float*)d_in[1];   // W_query (6,4)
    float* out = (float*)d_out;

    nerf_main<<<NBLK, BSZ>>>(tm, Wq, out);
    nerf_reduce<<<1, 1024>>>();
    nerf_norm<<<NRAYS / 256, 256>>>(out);
}

// round 2
// speedup vs baseline: 2.4110x; 2.4110x over previous
#include <cuda_runtime.h>

// Problem constants
#define BSZ    64
#define NRAYS  131072          // B*H*W = 2*256*256
#define NBLK   (NRAYS / BSZ)   // 2048
#define HW     65536
#define F_OFF  393216          // B*3*HW
#define D_OFF  786432          // 2*B*3*HW
#define STEP   (1.9f / 63.0f)

__device__ float g_rayd[NRAYS];
__device__ float g_pmin[NBLK];
__device__ float g_pmax[NBLK];

__device__ __forceinline__ float tanh_fast(float x) {
    float y;
    asm("tanh.approx.f32 %0, %1;" : "=f"(y) : "f"(x));
    return y;
}

// sigmoid(z) where z = 2*(d*sh + bh)  ->  0.5*tanh(d*sh+bh)+0.5
__device__ __forceinline__ float sig_of_t(float t) { return fmaf(0.5f, t, 0.5f); }

__global__ void __launch_bounds__(BSZ) nerf_main(
    const float* __restrict__ tm,   // transform_matrix (2,3,4)
    const float* __restrict__ Wq,   // W_query (6,4)
    float* __restrict__ out)
{
    __shared__ float sfd[64 * BSZ];   // fine depths (midpoints), [sample][tid]
    const int tid = threadIdx.x;
    const int r  = blockIdx.x * BSZ + tid;
    const int b  = r >> 16;
    const int n  = r & 65535;
    const int pi = n >> 8;
    const int pj = n & 255;

    float xv = 1.0f - (float)pj * (2.0f / 255.0f); if (pj == 255) xv = -1.0f;
    float yv = 1.0f - (float)pi * (2.0f / 255.0f); if (pi == 255) yv = -1.0f;
    float cx = xv / 4.2f;
    float cy = yv / 4.2f;

    const float* M = tm + b * 12;
    float ddx = M[0]*cx + M[1]*cy + M[2];
    float ddy = M[4]*cx + M[5]*cy + M[6];
    float ddz = M[8]*cx + M[9]*cy + M[10];
    float ox = M[3], oy = M[7], oz = M[11];

    // feat(d) = base + d*slope; pre-scale by 0.5 so sigmoid = 0.5*tanh(arg)+0.5
    float bh[4], sh[4];
    #pragma unroll
    for (int c = 0; c < 4; c++) {
        float w0 = Wq[c], w1 = Wq[4+c], w2 = Wq[8+c];
        float w3 = Wq[12+c], w4 = Wq[16+c], w5 = Wq[20+c];
        sh[c] = 0.5f * (ddx*w0 + ddy*w1 + ddz*w2);
        bh[c] = 0.5f * (ox*w0 + oy*w1 + oz*w2 + ddx*w3 + ddy*w4 + ddz*w5);
    }
    const float bh0 = bh[0], bh1 = bh[1], bh2 = bh[2], bh3 = bh[3];
    const float sh0 = sh[0], sh1 = sh[1], sh2 = sh[2], sh3 = sh[3];

    // ---- Pass 1: coarse ray march ----
    float T = 1.0f, a0 = 0.f, a1 = 0.f, a2 = 0.f, s = 0.f;
    {
        float dcur = 0.1f;
        #pragma unroll 8
        for (int p = 0; p < 64; p++) {
            float d  = (p == 63) ? 2.0f : dcur;
            float t0 = tanh_fast(fmaf(d, sh0, bh0));
            float op = sig_of_t(t0);
            float w  = op * T;
            T *= fmaf(-0.5f, t0, 0.5f);          // (1-op)
            a0 = fmaf(w, sig_of_t(tanh_fast(fmaf(d, sh1, bh1))), a0);
            a1 = fmaf(w, sig_of_t(tanh_fast(fmaf(d, sh2, bh2))), a1);
            a2 = fmaf(w, sig_of_t(tanh_fast(fmaf(d, sh3, bh3))), a2);
            s += w;
            dcur += STEP;
        }
    }
    s += 64.0f * 1e-5f;   // total of wpad

    // ---- Pass 2: streaming unnormalized CDF + inverse-CDF sampling ----
    // searchsorted(cumsum(wpad)/s, u, 'right') == searchsorted(cumsum(wpad), u*s)
    {
        const float su = s * (1.0f / 64.0f);
        float T2 = 1.0f, cprev = 0.0f, prevbin = 0.0f, dprev = 0.1f;
        float us = 0.0f;                         // u_k * s, incremental
        float dcur = 0.1f;
        int k = 0;
        for (int p = 0; p < 64; p++) {
            float d  = (p == 63) ? 2.0f : dcur;
            float t0 = tanh_fast(fmaf(d, sh0, bh0));
            float w  = sig_of_t(t0) * T2;
            T2 *= fmaf(-0.5f, t0, 0.5f);
            float cc = cprev + w + 1e-5f;
            while (k <= 64 && us < cc) {         // ind == p  (side='right')
                float bin;
                if (p == 0) {
                    bin = 0.1f;
                } else {
                    float t = __fdividef(us - cprev, cc - cprev);
                    t = fminf(fmaxf(t, 0.0f), 1.0f);
                    bin = fmaf(t, d - dprev, dprev);
                }
                if (k > 0) sfd[(k - 1) * BSZ + tid] = 0.5f * (prevbin + bin);
                prevbin = bin;
                k++;
                us += su;
            }
            cprev = cc;
            dprev = d;
            dcur += STEP;
        }
        while (k <= 64) {                        // ind == 64 -> depth[63] = FAR
            float bin = 2.0f;
            if (k > 0) sfd[(k - 1) * BSZ + tid] = 0.5f * (prevbin + bin);
            prevbin = bin;
            k++;
        }
    }

    // ---- Pass 3: merged (coarse U fine) march, register-cached merge heads ----
    float T3 = 1.0f, f0 = 0.f, f1 = 0.f, f2 = 0.f, fop = 0.f, accd = 0.f;
    {
        int pc = 0, pf = 0;
        float dc = 0.1f;
        float df = sfd[tid];
        int pfaddr = tid;
        #pragma unroll 4
        for (int m = 0; m < 128; m++) {
            bool cfirst = (pc < 64) && (dc <= df || pf >= 64);
            float d = cfirst ? dc : df;
            if (cfirst) {
                pc++;
                dc = (pc == 63) ? 2.0f : fmaf((float)pc, STEP, 0.1f);
            } else {
                pf++;
                pfaddr += BSZ;
                df = (pf < 64) ? sfd[pfaddr] : 3.0e38f;
            }
            float t0 = tanh_fast(fmaf(d, sh0, bh0));
            float w  = sig_of_t(t0) * T3;
            T3 *= fmaf(-0.5f, t0, 0.5f);
            f0 = fmaf(w, sig_of_t(tanh_fast(fmaf(d, sh1, bh1))), f0);
            f1 = fmaf(w, sig_of_t(tanh_fast(fmaf(d, sh2, bh2))), f1);
            f2 = fmaf(w, sig_of_t(tanh_fast(fmaf(d, sh3, bh3))), f2);
            fop += w;
            accd = fmaf(w, d, accd);
        }
    }
    fop = fminf(fop, 1.0f);
    float rayd = accd + (1.0f - fop) * 2.0f;   // d_all.max() == FAR globally

    // ---- Outputs ----
    out[(3*b + 0) * HW + n] = a0;
    out[(3*b + 1) * HW + n] = a1;
    out[(3*b + 2) * HW + n] = a2;
    out[F_OFF + (3*b + 0) * HW + n] = f0;
    out[F_OFF + (3*b + 1) * HW + n] = f1;
    out[F_OFF + (3*b + 2) * HW + n] = f2;
    g_rayd[r] = rayd;

    // ---- block min/max partials (2 warps) ----
    float mn = rayd, mx = rayd;
    #pragma unroll
    for (int o = 16; o; o >>= 1) {
        mn = fminf(mn, __shfl_xor_sync(0xffffffffu, mn, o));
        mx = fmaxf(mx, __shfl_xor_sync(0xffffffffu, mx, o));
    }
    __shared__ float smn[2], smx[2];
    if ((tid & 31) == 0) { smn[tid >> 5] = mn; smx[tid >> 5] = mx; }
    __syncthreads();
    if (tid == 0) {
        g_pmin[blockIdx.x] = fminf(mn, smn[1]);
        g_pmax[blockIdx.x] = fmaxf(mx, smx[1]);
    }
}

// Fused global min/max reduction + normalization. Each block redundantly
// reduces the 2048 partials (cheap, L2-resident), then normalizes 1024 rays.
__global__ void __launch_bounds__(1024) nerf_norm(float* __restrict__ out)
{
    const int t = threadIdx.x;
    float mn = fminf(g_pmin[t], g_pmin[t + 1024]);
    float mx = fmaxf(g_pmax[t], g_pmax[t + 1024]);
    #pragma unroll
    for (int o = 16; o; o >>= 1) {
        mn = fminf(mn, __shfl_xor_sync(0xffffffffu, mn, o));
        mx = fmaxf(mx, __shfl_xor_sync(0xffffffffu, mx, o));
    }
    __shared__ float smn[32], smx[32];
    __shared__ float bmn, bmx;
    if ((t & 31) == 0) { smn[t >> 5] = mn; smx[t >> 5] = mx; }
    __syncthreads();
    if (t < 32) {
        mn = smn[t];
        mx = smx[t];
        #pragma unroll
        for (int o = 16; o; o >>= 1) {
            mn = fminf(mn, __shfl_xor_sync(0xffffffffu, mn, o));
            mx = fmaxf(mx, __shfl_xor_sync(0xffffffffu, mx, o));
        }
        if (t == 0) { bmn = mn; bmx = mx; }
    }
    __syncthreads();
    const float lo = bmn, hi = bmx;
    const int r = blockIdx.x * 1024 + t;
    out[D_OFF + r] = (g_rayd[r] - lo) / (hi - lo);
}

extern "C" void kernel_launch(void* const* d_in, const int* in_sizes, int n_in,
                              void* d_out, int out_size)
{
    const float* tm = (const float*)d_in[0];   // transform_matrix (2,3,4)
    const float* Wq = (const float*)d_in[1];   // W_query (6,4)
    float* out = (float*)d_out;

    nerf_main<<<NBLK, BSZ>>>(tm, Wq, out);
    nerf_norm<<<NRAYS / 1024, 1024>>>(out);
}

// round 3
// speedup vs baseline: 2.5050x; 1.0390x over previous
#include <cuda_runtime.h>

// Problem constants
#define BSZ    64
#define NRAYS  131072          // B*H*W = 2*256*256
#define NBLK   (NRAYS / BSZ)   // 2048
#define HW     65536
#define F_OFF  393216          // B*3*HW
#define D_OFF  786432          // 2*B*3*HW
#define STEP   (1.9f / 63.0f)

__device__ float g_rayd[NRAYS];
__device__ float g_pmin[NBLK];
__device__ float g_pmax[NBLK];
__device__ float g_mm[2];      // {min, 1/(max-min)}

__device__ __forceinline__ float tanh_fast(float x) {
    float y;
    asm("tanh.approx.f32 %0, %1;" : "=f"(y) : "f"(x));
    return y;
}

__global__ void __launch_bounds__(BSZ, 12) nerf_main(
    const float* __restrict__ tm,   // transform_matrix (2,3,4)
    const float* __restrict__ Wq,   // W_query (6,4)
    float* __restrict__ out)
{
    __shared__ float sfd[64 * BSZ];   // fine depths (midpoints), [sample][tid]
    const int tid = threadIdx.x;
    const int r  = blockIdx.x * BSZ + tid;
    const int b  = r >> 16;
    const int n  = r & 65535;
    const int pi = n >> 8;
    const int pj = n & 255;

    float xv = 1.0f - (float)pj * (2.0f / 255.0f); if (pj == 255) xv = -1.0f;
    float yv = 1.0f - (float)pi * (2.0f / 255.0f); if (pi == 255) yv = -1.0f;
    float cx = xv / 4.2f;
    float cy = yv / 4.2f;

    const float* M = tm + b * 12;
    float ddx = M[0]*cx + M[1]*cy + M[2];
    float ddy = M[4]*cx + M[5]*cy + M[6];
    float ddz = M[8]*cx + M[9]*cy + M[10];
    float ox = M[3], oy = M[7], oz = M[11];

    // feat(d) = base + d*slope; pre-scaled by 0.5: sigmoid = 0.5*tanh(arg)+0.5
    float bh[4], sh[4];
    #pragma unroll
    for (int c = 0; c < 4; c++) {
        float w0 = Wq[c], w1 = Wq[4+c], w2 = Wq[8+c];
        float w3 = Wq[12+c], w4 = Wq[16+c], w5 = Wq[20+c];
        sh[c] = 0.5f * (ddx*w0 + ddy*w1 + ddz*w2);
        bh[c] = 0.5f * (ox*w0 + oy*w1 + oz*w2 + ddx*w3 + ddy*w4 + ddz*w5);
    }
    const float bh0 = bh[0], bh1 = bh[1], bh2 = bh[2], bh3 = bh[3];
    const float sh0 = sh[0], sh1 = sh[1], sh2 = sh[2], sh3 = sh[3];

    // ---- Pass 1: coarse march. u = T/2; w = fma(u,t0,u); colors as Sum(w*t).
    float u1 = 0.5f, A0 = 0.f, A1 = 0.f, A2 = 0.f, sw = 0.f;
    #pragma unroll
    for (int p = 0; p < 64; p++) {
        const float d = (p == 63) ? 2.0f : (0.1f + (float)p * STEP); // folds to imm
        float t0 = tanh_fast(fmaf(d, sh0, bh0));
        float t1 = tanh_fast(fmaf(d, sh1, bh1));
        float t2 = tanh_fast(fmaf(d, sh2, bh2));
        float t3 = tanh_fast(fmaf(d, sh3, bh3));
        float w  = fmaf(u1, t0, u1);          // w = op * T
        float hu = 0.5f * u1;
        u1 = fmaf(-hu, t0, hu);               // u' = T'(new)/2
        A0 = fmaf(w, t1, A0);
        A1 = fmaf(w, t2, A1);
        A2 = fmaf(w, t3, A2);
        sw += w;
    }
    const float a0 = 0.5f * (A0 + sw);
    const float a1 = 0.5f * (A1 + sw);
    const float a2 = 0.5f * (A2 + sw);
    const float s  = sw + 64.0f * 1e-5f;      // total of wpad

    // ---- Pass 2: streaming unnormalized CDF + inverse-CDF sampling ----
    // searchsorted(cumsum(wpad)/s, u, 'right') == searchsorted(cumsum(wpad), u*s)
    {
        const float su = s * (1.0f / 64.0f);
        float u2 = 0.5f, cprev = 0.0f, prevbin = 0.0f, dprev = 0.1f;
        float us = 0.0f;                      // u_k * s, incremental
        float dcur = 0.1f;
        int k = 0;
        for (int p = 0; p < 64; p++) {
            float d  = (p == 63) ? 2.0f : dcur;
            float t0 = tanh_fast(fmaf(d, sh0, bh0));
            float w  = fmaf(u2, t0, u2);
            float hu = 0.5f * u2;
            u2 = fmaf(-hu, t0, hu);
            float cc = cprev + w + 1e-5f;
            while (k <= 64 && us < cc) {      // ind == p (side='right')
                float bin;
                if (p == 0) {
                    bin = 0.1f;
                } else {
                    float t = __fdividef(us - cprev, cc - cprev);
                    t = fminf(fmaxf(t, 0.0f), 1.0f);
                    bin = fmaf(t, d - dprev, dprev);
                }
                if (k > 0) sfd[(k - 1) * BSZ + tid] = 0.5f * (prevbin + bin);
                prevbin = bin;
                k++;
                us += su;
            }
            cprev = cc;
            dprev = d;
            dcur += STEP;
        }
        while (k <= 64) {                     // ind == 64 -> depth[63] = FAR
            float bin = 2.0f;
            if (k > 0) sfd[(k - 1) * BSZ + tid] = 0.5f * (prevbin + bin);
            prevbin = bin;
            k++;
        }
    }

    // ---- Pass 3: merged (coarse U fine) march, incremental merge heads ----
    float u3 = 0.5f, F0 = 0.f, F1 = 0.f, F2 = 0.f, fsum = 0.f, accd = 0.f;
    {
        int pc = 0, pf = 0;
        float dc = 0.1f;
        float df = sfd[tid];
        int pfaddr = tid;
        #pragma unroll 4
        for (int m = 0; m < 128; m++) {
            bool cfirst = dc <= df;           // exhausted side parked at +INF
            float d = cfirst ? dc : df;
            if (cfirst) {
                pc++;
                dc = (pc >= 64) ? 3.0e38f : ((pc == 63) ? 2.0f : dc + STEP);
            } else {
                pf++;
                pfaddr += BSZ;
                df = (pf < 64) ? sfd[pfaddr] : 3.0e38f;
            }
            float t0 = tanh_fast(fmaf(d, sh0, bh0));
            float t1 = tanh_fast(fmaf(d, sh1, bh1));
            float t2 = tanh_fast(fmaf(d, sh2, bh2));
            float t3 = tanh_fast(fmaf(d, sh3, bh3));
            float w  = fmaf(u3, t0, u3);
            float hu = 0.5f * u3;
            u3 = fmaf(-hu, t0, hu);
            F0 = fmaf(w, t1, F0);
            F1 = fmaf(w, t2, F1);
            F2 = fmaf(w, t3, F2);
            fsum += w;
            accd = fmaf(w, d, accd);
        }
    }
    const float f0 = 0.5f * (F0 + fsum);
    const float f1 = 0.5f * (F1 + fsum);
    const float f2 = 0.5f * (F2 + fsum);
    float fop  = fminf(fsum, 1.0f);
    float rayd = accd + (1.0f - fop) * 2.0f;  // d_all.max() == FAR globally

    // ---- Outputs ----
    out[(3*b + 0) * HW + n] = a0;
    out[(3*b + 1) * HW + n] = a1;
    out[(3*b + 2) * HW + n] = a2;
    out[F_OFF + (3*b + 0) * HW + n] = f0;
    out[F_OFF + (3*b + 1) * HW + n] = f1;
    out[F_OFF + (3*b + 2) * HW + n] = f2;
    g_rayd[r] = rayd;

    // ---- block min/max partials (2 warps) ----
    float mn = rayd, mx = rayd;
    #pragma unroll
    for (int o = 16; o; o >>= 1) {
        mn = fminf(mn, __shfl_xor_sync(0xffffffffu, mn, o));
        mx = fmaxf(mx, __shfl_xor_sync(0xffffffffu, mx, o));
    }
    __shared__ float smn[2], smx[2];
    if ((tid & 31) == 0) { smn[tid >> 5] = mn; smx[tid >> 5] = mx; }
    __syncthreads();
    if (tid == 0) {
        g_pmin[blockIdx.x] = fminf(mn, smn[1]);
        g_pmax[blockIdx.x] = fmaxf(mx, smx[1]);
    }
}

// One-block global min/max over the 2048 partials; writes {min, 1/(max-min)}.
__global__ void __launch_bounds__(1024) nerf_reduce()
{
    const int t = threadIdx.x;
    float mn = fminf(g_pmin[t], g_pmin[t + 1024]);
    float mx = fmaxf(g_pmax[t], g_pmax[t + 1024]);
    #pragma unroll
    for (int o = 16; o; o >>= 1) {
        mn = fminf(mn, __shfl_xor_sync(0xffffffffu, mn, o));
        mx = fmaxf(mx, __shfl_xor_sync(0xffffffffu, mx, o));
    }
    __shared__ float smn[32], smx[32];
    if ((t & 31) == 0) { smn[t >> 5] = mn; smx[t >> 5] = mx; }
    __syncthreads();
    if (t < 32) {
        mn = smn[t];
        mx = smx[t];
        #pragma unroll
        for (int o = 16; o; o >>= 1) {
            mn = fminf(mn, __shfl_xor_sync(0xffffffffu, mn, o));
            mx = fmaxf(mx, __shfl_xor_sync(0xffffffffu, mx, o));
        }
        if (t == 0) { g_mm[0] = mn; g_mm[1] = 1.0f / (mx - mn); }
    }
}

// Vectorized normalize: 32768 threads x float4.
__global__ void __launch_bounds__(512) nerf_norm(float* __restrict__ out)
{
    const int i = blockIdx.x * 512 + threadIdx.x;
    const float mn = g_mm[0];
    const float sc = g_mm[1];
    float4 v = reinterpret_cast<const float4*>(g_rayd)[i];
    float4 o;
    o.x = (v.x - mn) * sc;
    o.y = (v.y - mn) * sc;
    o.z = (v.z - mn) * sc;
    o.w = (v.w - mn) * sc;
    reinterpret_cast<float4*>(out + D_OFF)[i] = o;
}

extern "C" void kernel_launch(void* const* d_in, const int* in_sizes, int n_in,
                              void* d_out, int out_size)
{
    const float* tm = (const float*)d_in[0];   // transform_matrix (2,3,4)
    const float* Wq = (const float*)d_in[1];   // W_query (6,4)
    float* out = (float*)d_out;

    nerf_main<<<NBLK, BSZ>>>(tm, Wq, out);
    nerf_reduce<<<1, 1024>>>();
    nerf_norm<<<NRAYS / 4 / 512, 512>>>(out);
}

// round 5
// speedup vs baseline: 2.5174x; 1.0050x over previous
#include <cuda_runtime.h>

// Problem constants
#define BSZ    64
#define NRAYS  131072          // B*H*W = 2*256*256
#define NBLK   (NRAYS / BSZ)   // 2048
#define HW     65536
#define F_OFF  393216          // B*3*HW
#define D_OFF  786432          // 2*B*3*HW
#define STEP   (1.9f / 63.0f)

__device__ float g_rayd[NRAYS];
__device__ float g_pmin[NBLK];
__device__ float g_pmax[NBLK];
__device__ float g_mm[2];      // {min, 1/(max-min)}

__device__ __forceinline__ float tanh_fast(float x) {
    float y;
    asm("tanh.approx.f32 %0, %1;" : "=f"(y) : "f"(x));
    return y;
}

// One merged-march sample step (tanh-form sigmoid; u = T/2)
#define SAMP(d)                                              \
    do {                                                     \
        float _d = (d);                                      \
        float t0 = tanh_fast(fmaf(_d, sh0, bh0));            \
        float t1 = tanh_fast(fmaf(_d, sh1, bh1));            \
        float t2 = tanh_fast(fmaf(_d, sh2, bh2));            \
        float t3 = tanh_fast(fmaf(_d, sh3, bh3));            \
        float w  = fmaf(u3, t0, u3);                         \
        float hu = 0.5f * u3;                                \
        u3 = fmaf(-hu, t0, hu);                              \
        F0 = fmaf(w, t1, F0);                                \
        F1 = fmaf(w, t2, F1);                                \
        F2 = fmaf(w, t3, F2);                                \
        fsum += w;                                           \
        accd = fmaf(w, _d, accd);                            \
    } while (0)

__global__ void __launch_bounds__(BSZ) nerf_main(
    const float* __restrict__ tm,   // transform_matrix (2,3,4)
    const float* __restrict__ Wq,   // W_query (6,4)
    float* __restrict__ out)
{
    // Per-thread column layout, stride BSZ (conflict-free):
    //   rows [0..63]   : coarse unnormalized CDF (cumsum of w + 1e-5)
    //   rows [64..127] : fine depths (midpoints)
    __shared__ float buf[128 * BSZ];
    const int tid = threadIdx.x;
    const int r  = blockIdx.x * BSZ + tid;
    const int b  = r >> 16;
    const int n  = r & 65535;
    const int pi = n >> 8;
    const int pj = n & 255;

    float xv = 1.0f - (float)pj * (2.0f / 255.0f); if (pj == 255) xv = -1.0f;
    float yv = 1.0f - (float)pi * (2.0f / 255.0f); if (pi == 255) yv = -1.0f;
    float cx = xv / 4.2f;
    float cy = yv / 4.2f;

    const float* M = tm + b * 12;
    float ddx = M[0]*cx + M[1]*cy + M[2];
    float ddy = M[4]*cx + M[5]*cy + M[6];
    float ddz = M[8]*cx + M[9]*cy + M[10];
    float ox = M[3], oy = M[7], oz = M[11];

    // feat(d) = base + d*slope; pre-scaled by 0.5: sigmoid = 0.5*tanh(arg)+0.5
    float bh[4], sh[4];
    #pragma unroll
    for (int c = 0; c < 4; c++) {
        float w0 = Wq[c], w1 = Wq[4+c], w2 = Wq[8+c];
        float w3 = Wq[12+c], w4 = Wq[16+c], w5 = Wq[20+c];
        sh[c] = 0.5f * (ddx*w0 + ddy*w1 + ddz*w2);
        bh[c] = 0.5f * (ox*w0 + oy*w1 + oz*w2 + ddx*w3 + ddy*w4 + ddz*w5);
    }
    const float bh0 = bh[0], bh1 = bh[1], bh2 = bh[2], bh3 = bh[3];
    const float sh0 = sh[0], sh1 = sh[1], sh2 = sh[2], sh3 = sh[3];

    // ---- Pass 1: coarse march, storing running cumsum(w + 1e-5) to smem ----
    float u1 = 0.5f, A0 = 0.f, A1 = 0.f, A2 = 0.f, cc1 = 0.f;
    {
        float dcur = 0.1f;
        int addr = tid;
        #pragma unroll 16
        for (int p = 0; p < 63; p++) {
            float t0 = tanh_fast(fmaf(dcur, sh0, bh0));
            float t1 = tanh_fast(fmaf(dcur, sh1, bh1));
            float t2 = tanh_fast(fmaf(dcur, sh2, bh2));
            float t3 = tanh_fast(fmaf(dcur, sh3, bh3));
            float w  = fmaf(u1, t0, u1);
            float hu = 0.5f * u1;
            u1 = fmaf(-hu, t0, hu);
            A0 = fmaf(w, t1, A0);
            A1 = fmaf(w, t2, A1);
            A2 = fmaf(w, t3, A2);
            cc1 += w + 1e-5f;
            buf[addr] = cc1;
            addr += BSZ;
            dcur += STEP;
        }
        { // peeled p = 63, d = FAR exactly
            float t0 = tanh_fast(fmaf(2.0f, sh0, bh0));
            float t1 = tanh_fast(fmaf(2.0f, sh1, bh1));
            float t2 = tanh_fast(fmaf(2.0f, sh2, bh2));
            float t3 = tanh_fast(fmaf(2.0f, sh3, bh3));
            float w  = fmaf(u1, t0, u1);
            float hu = 0.5f * u1;
            u1 = fmaf(-hu, t0, hu);
            A0 = fmaf(w, t1, A0);
            A1 = fmaf(w, t2, A1);
            A2 = fmaf(w, t3, A2);
            cc1 += w + 1e-5f;
            buf[addr] = cc1;
        }
    }
    const float s  = cc1;                      // total of wpad
    const float sw = cc1 - 64.0f * 1e-5f;      // total of w
    const float a0 = 0.5f * (A0 + sw);
    const float a1 = 0.5f * (A1 + sw);
    const float a2 = 0.5f * (A2 + sw);

    // ---- Pass 2: inverse-CDF sampling from stored cumsum (no tanh) ----
    // searchsorted(cumsum(wpad)/s, u, 'right') == searchsorted(cumsum(wpad), u*s)
    {
        const float su = s * (1.0f / 64.0f);
        float cprev = 0.0f, prevbin = 0.0f, dprev = 0.1f;
        float us = 0.0f;                       // u_k * s, incremental
        float dcur = 0.1f;
        int raddr = tid;
        int waddr = 64 * BSZ + tid;
        int k = 0;
        #pragma unroll 4
        for (int p = 0; p < 64; p++) {
            float d  = (p == 63) ? 2.0f : dcur;
            float cc = buf[raddr];
            raddr += BSZ;
            while (k <= 64 && us < cc) {       // ind == p (side='right')
                float bin;
                if (p == 0) {
                    bin = 0.1f;
                } else {
                    float t = __fdividef(us - cprev, cc - cprev);
                    t = fminf(fmaxf(t, 0.0f), 1.0f);
                    bin = fmaf(t, d - dprev, dprev);
                }
                if (k > 0) { buf[waddr] = 0.5f * (prevbin + bin); waddr += BSZ; }
                prevbin = bin;
                k++;
                us += su;
            }
            cprev = cc;
            dprev = d;
            dcur += STEP;
        }
        while (k <= 64) {                      // ind == 64 -> depth[63] = FAR
            float bin = 2.0f;
            if (k > 0) { buf[waddr] = 0.5f * (prevbin + bin); waddr += BSZ; }
            prevbin = bin;
            k++;
        }
    }

    // ---- Pass 3: merged march, coarse-outer / fine-inner ----
    float u3 = 0.5f, F0 = 0.f, F1 = 0.f, F2 = 0.f, fsum = 0.f, accd = 0.f;
    {
        int pf = 0;
        int faddr = 64 * BSZ + tid;
        float df = buf[faddr];
        float dcur = 0.1f;
        #pragma unroll 8
        for (int p = 0; p < 63; p++) {
            while (pf < 64 && df < dcur) {     // fine strictly before coarse (ties -> coarse)
                SAMP(df);
                pf++;
                faddr += BSZ;
                df = (pf < 64) ? buf[faddr] : 3.0e38f;   // guarded reload (no OOB)
            }
            SAMP(dcur);
            dcur += STEP;
        }
        { // peeled coarse p = 63, d = FAR
            while (pf < 64 && df < 2.0f) {
                SAMP(df);
                pf++;
                faddr += BSZ;
                df = (pf < 64) ? buf[faddr] : 3.0e38f;
            }
            SAMP(2.0f);
        }
        while (pf < 64) {                      // remaining fine (== FAR midpoints)
            SAMP(df);
            pf++;
            faddr += BSZ;
            df = (pf < 64) ? buf[faddr] : 3.0e38f;
        }
    }
    const float f0 = 0.5f * (F0 + fsum);
    const float f1 = 0.5f * (F1 + fsum);
    const float f2 = 0.5f * (F2 + fsum);
    float fop  = fminf(fsum, 1.0f);
    float rayd = accd + (1.0f - fop) * 2.0f;   // d_all.max() == FAR globally

    // ---- Outputs ----
    out[(3*b + 0) * HW + n] = a0;
    out[(3*b + 1) * HW + n] = a1;
    out[(3*b + 2) * HW + n] = a2;
    out[F_OFF + (3*b + 0) * HW + n] = f0;
    out[F_OFF + (3*b + 1) * HW + n] = f1;
    out[F_OFF + (3*b + 2) * HW + n] = f2;
    g_rayd[r] = rayd;

    // ---- block min/max partials (2 warps) ----
    float mn = rayd, mx = rayd;
    #pragma unroll
    for (int o = 16; o; o >>= 1) {
        mn = fminf(mn, __shfl_xor_sync(0xffffffffu, mn, o));
        mx = fmaxf(mx, __shfl_xor_sync(0xffffffffu, mx, o));
    }
    __shared__ float smn[2], smx[2];
    if ((tid & 31) == 0) { smn[tid >> 5] = mn; smx[tid >> 5] = mx; }
    __syncthreads();
    if (tid == 0) {
        g_pmin[blockIdx.x] = fminf(mn, smn[1]);
        g_pmax[blockIdx.x] = fmaxf(mx, smx[1]);
    }
}

// One-block global min/max over the 2048 partials; writes {min, 1/(max-min)}.
__global__ void __launch_bounds__(1024) nerf_reduce()
{
    const int t = threadIdx.x;
    float mn = fminf(g_pmin[t], g_pmin[t + 1024]);
    float mx = fmaxf(g_pmax[t], g_pmax[t + 1024]);
    #pragma unroll
    for (int o = 16; o; o >>= 1) {
        mn = fminf(mn, __shfl_xor_sync(0xffffffffu, mn, o));
        mx = fmaxf(mx, __shfl_xor_sync(0xffffffffu, mx, o));
    }
    __shared__ float smn[32], smx[32];
    if ((t & 31) == 0) { smn[t >> 5] = mn; smx[t >> 5] = mx; }
    __syncthreads();
    if (t < 32) {
        mn = smn[t];
        mx = smx[t];
        #pragma unroll
        for (int o = 16; o; o >>= 1) {
            mn = fminf(mn, __shfl_xor_sync(0xffffffffu, mn, o));
            mx = fmaxf(mx, __shfl_xor_sync(0xffffffffu, mx, o));
        }
        if (t == 0) { g_mm[0] = mn; g_mm[1] = 1.0f / (mx - mn); }
    }
}

// Vectorized normalize: 32768 threads x float4.
__global__ void __launch_bounds__(512) nerf_norm(float* __restrict__ out)
{
    const int i = blockIdx.x * 512 + threadIdx.x;
    const float mn = g_mm[0];
    const float sc = g_mm[1];
    float4 v = reinterpret_cast<const float4*>(g_rayd)[i];
    float4 o;
    o.x = (v.x - mn) * sc;
    o.y = (v.y - mn) * sc;
    o.z = (v.z - mn) * sc;
    o.w = (v.w - mn) * sc;
    reinterpret_cast<float4*>(out + D_OFF)[i] = o;
}

extern "C" void kernel_launch(void* const* d_in, const int* in_sizes, int n_in,
                              void* d_out, int out_size)
{
    const float* tm = (const float*)d_in[0];   // transform_matrix (2,3,4)
    const float* Wq = (const float*)d_in[1];   // W_query (6,4)
    float* out = (float*)d_out;

    nerf_main<<<NBLK, BSZ>>>(tm, Wq, out);
    nerf_reduce<<<1, 1024>>>();
    nerf_norm<<<NRAYS / 4 / 512, 512>>>(out);
}

// round 6
// speedup vs baseline: 2.6082x; 1.0361x over previous
#include <cuda_runtime.h>

// Problem constants
#define BSZ    64
#define NRAYS  131072          // B*H*W = 2*256*256
#define NBLK   (NRAYS / BSZ)   // 2048
#define HW     65536
#define F_OFF  393216          // B*3*HW
#define D_OFF  786432          // 2*B*3*HW
#define STEP   (1.9f / 63.0f)

__device__ float g_rayd[NRAYS];
__device__ float g_pmin[NBLK];
__device__ float g_pmax[NBLK];
__device__ float g_mm[2];      // {min, 1/(max-min)}

__device__ __forceinline__ float tanh_fast(float x) {
    float y;
    asm("tanh.approx.f32 %0, %1;" : "=f"(y) : "f"(x));
    return y;
}

// One merged-march sample step (tanh-form sigmoid; u = T/2)
#define SAMP(d)                                              \
    do {                                                     \
        float _d = (d);                                      \
        float t0 = tanh_fast(fmaf(_d, sh0, bh0));            \
        float t1 = tanh_fast(fmaf(_d, sh1, bh1));            \
        float t2 = tanh_fast(fmaf(_d, sh2, bh2));            \
        float t3 = tanh_fast(fmaf(_d, sh3, bh3));            \
        float w  = fmaf(u3, t0, u3);                         \
        float hu = 0.5f * u3;                                \
        u3 = fmaf(-hu, t0, hu);                              \
        F0 = fmaf(w, t1, F0);                                \
        F1 = fmaf(w, t2, F1);                                \
        F2 = fmaf(w, t3, F2);                                \
        fsum += w;                                           \
        accd = fmaf(w, _d, accd);                            \
    } while (0)

// Advance coarse march pointer: emit all coarse samples with depth <= lim
#define DRAIN_COARSE(lim)                                    \
    while (pc < 64 && dc <= (lim)) {                         \
        SAMP(dc);                                            \
        pc++;                                                \
        dc = (pc == 63) ? 2.0f : dc + STEP;                  \
    }

__global__ void __launch_bounds__(BSZ) nerf_main(
    const float* __restrict__ tm,   // transform_matrix (2,3,4)
    const float* __restrict__ Wq,   // W_query (6,4)
    float* __restrict__ out)
{
    // Per-thread column, stride BSZ (conflict-free): coarse unnormalized CDF
    __shared__ float buf[64 * BSZ];
    const int tid = threadIdx.x;
    const int r  = blockIdx.x * BSZ + tid;
    const int b  = r >> 16;
    const int n  = r & 65535;
    const int pi = n >> 8;
    const int pj = n & 255;

    float xv = 1.0f - (float)pj * (2.0f / 255.0f); if (pj == 255) xv = -1.0f;
    float yv = 1.0f - (float)pi * (2.0f / 255.0f); if (pi == 255) yv = -1.0f;
    float cx = xv / 4.2f;
    float cy = yv / 4.2f;

    const float* M = tm + b * 12;
    float ddx = M[0]*cx + M[1]*cy + M[2];
    float ddy = M[4]*cx + M[5]*cy + M[6];
    float ddz = M[8]*cx + M[9]*cy + M[10];
    float ox = M[3], oy = M[7], oz = M[11];

    // feat(d) = base + d*slope; pre-scaled by 0.5: sigmoid = 0.5*tanh(arg)+0.5
    float bh[4], sh[4];
    #pragma unroll
    for (int c = 0; c < 4; c++) {
        float w0 = Wq[c], w1 = Wq[4+c], w2 = Wq[8+c];
        float w3 = Wq[12+c], w4 = Wq[16+c], w5 = Wq[20+c];
        sh[c] = 0.5f * (ddx*w0 + ddy*w1 + ddz*w2);
        bh[c] = 0.5f * (ox*w0 + oy*w1 + oz*w2 + ddx*w3 + ddy*w4 + ddz*w5);
    }
    const float bh0 = bh[0], bh1 = bh[1], bh2 = bh[2], bh3 = bh[3];
    const float sh0 = sh[0], sh1 = sh[1], sh2 = sh[2], sh3 = sh[3];

    // ---- Pass 1: coarse march, storing running cumsum(w + 1e-5) to smem ----
    float u1 = 0.5f, A0 = 0.f, A1 = 0.f, A2 = 0.f, cc1 = 0.f;
    {
        float dcur = 0.1f;
        int addr = tid;
        #pragma unroll 16
        for (int p = 0; p < 64; p++) {
            float d  = (p == 63) ? 2.0f : dcur;
            float t0 = tanh_fast(fmaf(d, sh0, bh0));
            float t1 = tanh_fast(fmaf(d, sh1, bh1));
            float t2 = tanh_fast(fmaf(d, sh2, bh2));
            float t3 = tanh_fast(fmaf(d, sh3, bh3));
            float w  = fmaf(u1, t0, u1);
            float hu = 0.5f * u1;
            u1 = fmaf(-hu, t0, hu);
            A0 = fmaf(w, t1, A0);
            A1 = fmaf(w, t2, A1);
            A2 = fmaf(w, t3, A2);
            cc1 += w + 1e-5f;
            buf[addr] = cc1;
            addr += BSZ;
            dcur += STEP;
        }
    }
    const float s  = cc1;                      // total of wpad
    const float sw = cc1 - 64.0f * 1e-5f;      // total of w
    const float a0 = 0.5f * (A0 + sw);
    const float a1 = 0.5f * (A1 + sw);
    const float a2 = 0.5f * (A2 + sw);

    // ---- Pass 2+3 fused: inverse-CDF sampling feeding the merged march ----
    // searchsorted(cumsum(wpad)/s, u, 'right') == searchsorted(cumsum(wpad), u*s)
    // Fine midpoints come out in non-decreasing depth order; the merged march
    // consumes each immediately, draining pending coarse samples first
    // (coarse-first on ties == stable argsort of concat(coarse, fine)).
    float u3 = 0.5f, F0 = 0.f, F1 = 0.f, F2 = 0.f, fsum = 0.f, accd = 0.f;
    {
        const float su = s * (1.0f / 64.0f);
        float cprev = 0.0f, prevbin = 0.0f, dprev = 0.1f;
        float us = 0.0f;                       // u_k * s, incremental
        float dcur = 0.1f;                     // CDF-bin depth walker
        float dc = 0.1f;                       // march coarse depth walker
        int k = 0, pc = 0;
        int raddr = tid;
        #pragma unroll 1
        for (int p = 0; p < 64; p++) {
            float d  = (p == 63) ? 2.0f : dcur;
            float cc = buf[raddr];
            raddr += BSZ;
            while (k <= 64 && us < cc) {       // ind == p (side='right')
                float bin;
                if (p == 0) {
                    bin = 0.1f;
                } else {
                    float t = __fdividef(us - cprev, cc - cprev);
                    t = fminf(fmaxf(t, 0.0f), 1.0f);
                    bin = fmaf(t, d - dprev, dprev);
                }
                if (k > 0) {
                    float m = 0.5f * (prevbin + bin);  // fine midpoint (sorted)
                    DRAIN_COARSE(m);
                    SAMP(m);
                }
                prevbin = bin;
                k++;
                us += su;
            }
            cprev = cc;
            dprev = d;
            dcur += STEP;
        }
        while (k <= 64) {                      // ind == 64 -> depth[63] = FAR
            float bin = 2.0f;
            if (k > 0) {
                float m = 0.5f * (prevbin + bin);
                DRAIN_COARSE(m);
                SAMP(m);
            }
            prevbin = bin;
            k++;
        }
        DRAIN_COARSE(3.0e38f);                 // flush remaining coarse
    }
    const float f0 = 0.5f * (F0 + fsum);
    const float f1 = 0.5f * (F1 + fsum);
    const float f2 = 0.5f * (F2 + fsum);
    float fop  = fminf(fsum, 1.0f);
    float rayd = accd + (1.0f - fop) * 2.0f;   // d_all.max() == FAR globally

    // ---- Outputs ----
    out[(3*b + 0) * HW + n] = a0;
    out[(3*b + 1) * HW + n] = a1;
    out[(3*b + 2) * HW + n] = a2;
    out[F_OFF + (3*b + 0) * HW + n] = f0;
    out[F_OFF + (3*b + 1) * HW + n] = f1;
    out[F_OFF + (3*b + 2) * HW + n] = f2;
    g_rayd[r] = rayd;

    // ---- block min/max partials (2 warps) ----
    float mn = rayd, mx = rayd;
    #pragma unroll
    for (int o = 16; o; o >>= 1) {
        mn = fminf(mn, __shfl_xor_sync(0xffffffffu, mn, o));
        mx = fmaxf(mx, __shfl_xor_sync(0xffffffffu, mx, o));
    }
    __shared__ float smn[2], smx[2];
    if ((tid & 31) == 0) { smn[tid >> 5] = mn; smx[tid >> 5] = mx; }
    __syncthreads();
    if (tid == 0) {
        g_pmin[blockIdx.x] = fminf(mn, smn[1]);
        g_pmax[blockIdx.x] = fmaxf(mx, smx[1]);
    }
}

// One-block global min/max over the 2048 partials; writes {min, 1/(max-min)}.
__global__ void __launch_bounds__(1024) nerf_reduce()
{
    const int t = threadIdx.x;
    float mn = fminf(g_pmin[t], g_pmin[t + 1024]);
    float mx = fmaxf(g_pmax[t], g_pmax[t + 1024]);
    #pragma unroll
    for (int o = 16; o; o >>= 1) {
        mn = fminf(mn, __shfl_xor_sync(0xffffffffu, mn, o));
        mx = fmaxf(mx, __shfl_xor_sync(0xffffffffu, mx, o));
    }
    __shared__ float smn[32], smx[32];
    if ((t & 31) == 0) { smn[t >> 5] = mn; smx[t >> 5] = mx; }
    __syncthreads();
    if (t < 32) {
        mn = smn[t];
        mx = smx[t];
        #pragma unroll
        for (int o = 16; o; o >>= 1) {
            mn = fminf(mn, __shfl_xor_sync(0xffffffffu, mn, o));
            mx = fmaxf(mx, __shfl_xor_sync(0xffffffffu, mx, o));
        }
        if (t == 0) { g_mm[0] = mn; g_mm[1] = 1.0f / (mx - mn); }
    }
}

// Vectorized normalize: 32768 threads x float4.
__global__ void __launch_bounds__(512) nerf_norm(float* __restrict__ out)
{
    const int i = blockIdx.x * 512 + threadIdx.x;
    const float mn = g_mm[0];
    const float sc = g_mm[1];
    float4 v = reinterpret_cast<const float4*>(g_rayd)[i];
    float4 o;
    o.x = (v.x - mn) * sc;
    o.y = (v.y - mn) * sc;
    o.z = (v.z - mn) * sc;
    o.w = (v.w - mn) * sc;
    reinterpret_cast<float4*>(out + D_OFF)[i] = o;
}

extern "C" void kernel_launch(void* const* d_in, const int* in_sizes, int n_in,
                              void* d_out, int out_size)
{
    const float* tm = (const float*)d_in[0];   // transform_matrix (2,3,4)
    const float* Wq = (const float*)d_in[1];   // W_query (6,4)
    float* out = (float*)d_out;

    nerf_main<<<NBLK, BSZ>>>(tm, Wq, out);
    nerf_reduce<<<1, 1024>>>();
    nerf_norm<<<NRAYS / 4 / 512, 512>>>(out);
}

// round 9
// speedup vs baseline: 2.7223x; 1.0437x over previous
#include <cuda_runtime.h>

// Problem constants
#define BSZ    64
#define NRAYS  131072          // B*H*W = 2*256*256
#define NBLK   (NRAYS / BSZ)   // 2048
#define HW     65536
#define F_OFF  393216          // B*3*HW
#define D_OFF  786432          // 2*B*3*HW
#define STEP   (1.9f / 63.0f)

__device__ float g_rayd[NRAYS];
__device__ float g_pmin[NBLK];
__device__ float g_pmax[NBLK];
__device__ float g_mm[2];      // {min, 1/(max-min)}

__device__ __forceinline__ float tanh_fast(float x) {
    float y;
    asm("tanh.approx.f32 %0, %1;" : "=f"(y) : "f"(x));
    return y;
}

#define PACK2(out, lo, hi) \
    asm("mov.b64 %0, {%1, %2};" : "=l"(out) : "f"(lo), "f"(hi))
#define UNPACK2(lo, hi, in) \
    asm("mov.b64 {%0, %1}, %2;" : "=f"(lo), "=f"(hi) : "l"(in))
#define FMA2(out, a, b, c) \
    asm("fma.rn.f32x2 %0, %1, %2, %3;" : "=l"(out) : "l"(a), "l"(b), "l"(c))

// One merged-march sample step.
// u = T/2; w = u*(1+t0); T' = T*(1-op) -> u' = u - w/2 (single fma).
#define SAMP(d)                                              \
    do {                                                     \
        float _d = (d);                                      \
        unsigned long long D2, G01, G23;                     \
        PACK2(D2, _d, _d);                                   \
        FMA2(G01, D2, SH01, BH01);                           \
        FMA2(G23, D2, SH23, BH23);                           \
        float g0, g1, g2, g3;                                \
        UNPACK2(g0, g1, G01);                                \
        UNPACK2(g2, g3, G23);                                \
        float t0 = tanh_fast(g0);                            \
        float t1 = tanh_fast(g1);                            \
        float t2 = tanh_fast(g2);                            \
        float t3 = tanh_fast(g3);                            \
        float w  = fmaf(u3, t0, u3);                         \
        u3 = fmaf(-0.5f, w, u3);                             \
        F0 = fmaf(w, t1, F0);                                \
        F1 = fmaf(w, t2, F1);                                \
        F2 = fmaf(w, t3, F2);                                \
        accd = fmaf(w, _d, accd);                            \
    } while (0)

// Emit all coarse samples with depth <= lim
#define DRAIN_COARSE(lim)                                    \
    while (pc < 64 && dc <= (lim)) {                         \
        SAMP(dc);                                            \
        pc++;                                                \
        dc = (pc == 63) ? 2.0f : dc + STEP;                  \
    }

__global__ void __launch_bounds__(BSZ) nerf_main(
    const float* __restrict__ tm,   // transform_matrix (2,3,4)
    const float* __restrict__ Wq,   // W_query (6,4)
    float* __restrict__ out)
{
    // Per-thread column, stride BSZ (conflict-free): coarse unnormalized CDF
    __shared__ float buf[64 * BSZ];
    const int tid = threadIdx.x;
    const int r  = blockIdx.x * BSZ + tid;
    const int b  = r >> 16;
    const int n  = r & 65535;
    const int pi = n >> 8;
    const int pj = n & 255;

    float xv = 1.0f - (float)pj * (2.0f / 255.0f); if (pj == 255) xv = -1.0f;
    float yv = 1.0f - (float)pi * (2.0f / 255.0f); if (pi == 255) yv = -1.0f;
    float cx = xv / 4.2f;
    float cy = yv / 4.2f;

    const float* M = tm + b * 12;
    float ddx = M[0]*cx + M[1]*cy + M[2];
    float ddy = M[4]*cx + M[5]*cy + M[6];
    float ddz = M[8]*cx + M[9]*cy + M[10];
    float ox = M[3], oy = M[7], oz = M[11];

    // feat(d) = base + d*slope; pre-scaled by 0.5: sigmoid = 0.5*tanh(arg)+0.5
    float bh[4], sh[4];
    #pragma unroll
    for (int c = 0; c < 4; c++) {
        float w0 = Wq[c], w1 = Wq[4+c], w2 = Wq[8+c];
        float w3 = Wq[12+c], w4 = Wq[16+c], w5 = Wq[20+c];
        sh[c] = 0.5f * (ddx*w0 + ddy*w1 + ddz*w2);
        bh[c] = 0.5f * (ox*w0 + oy*w1 + oz*w2 + ddx*w3 + ddy*w4 + ddz*w5);
    }
    unsigned long long SH01, SH23, BH01, BH23;
    PACK2(SH01, sh[0], sh[1]);
    PACK2(SH23, sh[2], sh[3]);
    PACK2(BH01, bh[0], bh[1]);
    PACK2(BH23, bh[2], bh[3]);

    // ---- Pass 1: coarse march, storing running cumsum(w + 1e-5) to smem ----
    float u1 = 0.5f, A0 = 0.f, A1 = 0.f, A2 = 0.f, cc1 = 0.f;
    {
        float dcur = 0.1f;
        int addr = tid;
        #pragma unroll 16
        for (int p = 0; p < 64; p++) {
            float d  = (p == 63) ? 2.0f : dcur;
            unsigned long long D2, G01, G23;
            PACK2(D2, d, d);
            FMA2(G01, D2, SH01, BH01);
            FMA2(G23, D2, SH23, BH23);
            float g0, g1, g2, g3;
            UNPACK2(g0, g1, G01);
            UNPACK2(g2, g3, G23);
            float t0 = tanh_fast(g0);
            float t1 = tanh_fast(g1);
            float t2 = tanh_fast(g2);
            float t3 = tanh_fast(g3);
            float w  = fmaf(u1, t0, u1);
            u1 = fmaf(-0.5f, w, u1);
            A0 = fmaf(w, t1, A0);
            A1 = fmaf(w, t2, A1);
            A2 = fmaf(w, t3, A2);
            cc1 += w + 1e-5f;
            buf[addr] = cc1;
            addr += BSZ;
            dcur += STEP;
        }
    }
    const float s  = cc1;                      // total of wpad
    // Sum(w) = 1 - T = 1 - 2*u1; a = 0.5*(A + Sum(w))
    const float h1 = 0.5f - u1;
    const float a0 = fmaf(0.5f, A0, h1);
    const float a1 = fmaf(0.5f, A1, h1);
    const float a2 = fmaf(0.5f, A2, h1);

    // ---- Pass 2+3 fused: inverse-CDF sampling feeding the merged march ----
    // searchsorted(cumsum(wpad)/s, u, 'right') == searchsorted(cumsum(wpad), u*s)
    // Fine midpoints emerge in non-decreasing depth order; consume immediately,
    // draining pending coarse samples first (coarse-first on ties == stable sort).
    float u3 = 0.5f, F0 = 0.f, F1 = 0.f, F2 = 0.f, accd = 0.f;
    {
        const float su = s * (1.0f / 64.0f);
        float cprev = 0.0f, prevbin = 0.0f, dprev = 0.1f;
        float us = 0.0f;                       // u_k * s, incremental
        float dcur = 0.1f;                     // CDF-bin depth walker
        float dc = 0.1f;                       // march coarse depth walker
        int k = 0, pc = 0;
        int raddr = tid;
        #pragma unroll 1
        for (int p = 0; p < 64; p++) {
            float d  = (p == 63) ? 2.0f : dcur;
            float cc = buf[raddr];
            raddr += BSZ;
            while (k <= 64 && us < cc) {       // ind == p (side='right')
                float bin;
                if (p == 0) {
                    bin = 0.1f;
                } else {
                    float t = __fdividef(us - cprev, cc - cprev);
                    t = fminf(fmaxf(t, 0.0f), 1.0f);
                    bin = fmaf(t, d - dprev, dprev);
                }
                if (k > 0) {
                    float m = 0.5f * (prevbin + bin);  // fine midpoint (sorted)
                    DRAIN_COARSE(m);
                    SAMP(m);
                }
                prevbin = bin;
                k++;
                us += su;
            }
            cprev = cc;
            dprev = d;
            dcur += STEP;
        }
        while (k <= 64) {                      // ind == 64 -> depth[63] = FAR
            float bin = 2.0f;
            if (k > 0) {
                float m = 0.5f * (prevbin + bin);
                DRAIN_COARSE(m);
                SAMP(m);
            }
            prevbin = bin;
            k++;
        }
        DRAIN_COARSE(3.0e38f);                 // flush remaining coarse
    }
    const float fsum = 1.0f - 2.0f * u3;       // Sum(w) over merged march
    const float h3 = 0.5f - u3;
    const float f0 = fmaf(0.5f, F0, h3);
    const float f1 = fmaf(0.5f, F1, h3);
    const float f2 = fmaf(0.5f, F2, h3);
    float fop  = fminf(fsum, 1.0f);
    float rayd = accd + (1.0f - fop) * 2.0f;   // d_all.max() == FAR globally

    // ---- Outputs ----
    out[(3*b + 0) * HW + n] = a0;
    out[(3*b + 1) * HW + n] = a1;
    out[(3*b + 2) * HW + n] = a2;
    out[F_OFF + (3*b + 0) * HW + n] = f0;
    out[F_OFF + (3*b + 1) * HW + n] = f1;
    out[F_OFF + (3*b + 2) * HW + n] = f2;
    g_rayd[r] = rayd;

    // ---- block min/max partials (2 warps) ----
    float mn = rayd, mx = rayd;
    #pragma unroll
    for (int o = 16; o; o >>= 1) {
        mn = fminf(mn, __shfl_xor_sync(0xffffffffu, mn, o));
        mx = fmaxf(mx, __shfl_xor_sync(0xffffffffu, mx, o));
    }
    __shared__ float smn[2], smx[2];
    if ((tid & 31) == 0) { smn[tid >> 5] = mn; smx[tid >> 5] = mx; }
    __syncthreads();
    if (tid == 0) {
        g_pmin[blockIdx.x] = fminf(mn, smn[1]);
        g_pmax[blockIdx.x] = fmaxf(mx, smx[1]);
    }
}

// One-block global min/max over the 2048 partials; writes {min, 1/(max-min)}.
__global__ void __launch_bounds__(1024) nerf_reduce()
{
    const int t = threadIdx.x;
    float mn = fminf(g_pmin[t], g_pmin[t + 1024]);
    float mx = fmaxf(g_pmax[t], g_pmax[t + 1024]);
    #pragma unroll
    for (int o = 16; o; o >>= 1) {
        mn = fminf(mn, __shfl_xor_sync(0xffffffffu, mn, o));
        mx = fmaxf(mx, __shfl_xor_sync(0xffffffffu, mx, o));
    }
    __shared__ float smn[32], smx[32];
    if ((t & 31) == 0) { smn[t >> 5] = mn; smx[t >> 5] = mx; }
    __syncthreads();
    if (t < 32) {
        mn = smn[t];
        mx = smx[t];
        #pragma unroll
        for (int o = 16; o; o >>= 1) {
            mn = fminf(mn, __shfl_xor_sync(0xffffffffu, mn, o));
            mx = fmaxf(mx, __shfl_xor_sync(0xffffffffu, mx, o));
        }
        if (t == 0) { g_mm[0] = mn; g_mm[1] = 1.0f / (mx - mn); }
    }
}

// Vectorized normalize: 32768 threads x float4.
__global__ void __launch_bounds__(512) nerf_norm(float* __restrict__ out)
{
    const int i = blockIdx.x * 512 + threadIdx.x;
    const float mn = g_mm[0];
    const float sc = g_mm[1];
    float4 v = reinterpret_cast<const float4*>(g_rayd)[i];
    float4 o;
    o.x = (v.x - mn) * sc;
    o.y = (v.y - mn) * sc;
    o.z = (v.z - mn) * sc;
    o.w = (v.w - mn) * sc;
    reinterpret_cast<float4*>(out + D_OFF)[i] = o;
}

extern "C" void kernel_launch(void* const* d_in, const int* in_sizes, int n_in,
                              void* d_out, int out_size)
{
    const float* tm = (const float*)d_in[0];   // transform_matrix (2,3,4)
    const float* Wq = (const float*)d_in[1];   // W_query (6,4)
    float* out = (float*)d_out;

    nerf_main<<<NBLK, BSZ>>>(tm, Wq, out);
    nerf_reduce<<<1, 1024>>>();
    nerf_norm<<<NRAYS / 4 / 512, 512>>>(out);
}

// round 10
// speedup vs baseline: 2.7388x; 1.0061x over previous
#include <cuda_runtime.h>

// Problem constants
#define BSZ    64
#define NRAYS  131072          // B*H*W = 2*256*256
#define NBLK   (NRAYS / BSZ)   // 2048
#define HW     65536
#define F_OFF  393216          // B*3*HW
#define D_OFF  786432          // 2*B*3*HW
#define STEP   (1.9f / 63.0f)

__device__ float g_rayd[NRAYS];
__device__ float g_pmin[NBLK];
__device__ float g_pmax[NBLK];
__device__ float g_mm[2];      // {min, 1/(max-min)}

__device__ __forceinline__ float tanh_fast(float x) {
    float y;
    asm("tanh.approx.f32 %0, %1;" : "=f"(y) : "f"(x));
    return y;
}

#define PACK2(out, lo, hi) \
    asm("mov.b64 %0, {%1, %2};" : "=l"(out) : "f"(lo), "f"(hi))
#define UNPACK2(lo, hi, in) \
    asm("mov.b64 {%0, %1}, %2;" : "=f"(lo), "=f"(hi) : "l"(in))
#define FMA2(out, a, b, c) \
    asm("fma.rn.f32x2 %0, %1, %2, %3;" : "=l"(out) : "l"(a), "l"(b), "l"(c))

// One merged-march sample step.
// u = T/2; w = u*(1+t0); T' = T*(1-op) -> u' = u - w/2 (single fma).
#define SAMP(d)                                              \
    do {                                                     \
        float _d = (d);                                      \
        unsigned long long D2, G01, G23;                     \
        PACK2(D2, _d, _d);                                   \
        FMA2(G01, D2, SH01, BH01);                           \
        FMA2(G23, D2, SH23, BH23);                           \
        float g0, g1, g2, g3;                                \
        UNPACK2(g0, g1, G01);                                \
        UNPACK2(g2, g3, G23);                                \
        float t0 = tanh_fast(g0);                            \
        float t1 = tanh_fast(g1);                            \
        float t2 = tanh_fast(g2);                            \
        float t3 = tanh_fast(g3);                            \
        float w  = fmaf(u3, t0, u3);                         \
        u3 = fmaf(-0.5f, w, u3);                             \
        F0 = fmaf(w, t1, F0);                                \
        F1 = fmaf(w, t2, F1);                                \
        F2 = fmaf(w, t3, F2);                                \
        accd = fmaf(w, _d, accd);                            \
    } while (0)

// Emit all coarse samples with depth <= lim
#define DRAIN_COARSE(lim)                                    \
    while (pc < 64 && dc <= (lim)) {                         \
        SAMP(dc);                                            \
        pc++;                                                \
        dc = (pc == 63) ? 2.0f : dc + STEP;                  \
    }

__global__ void __launch_bounds__(BSZ, 14) nerf_main(
    const float* __restrict__ tm,   // transform_matrix (2,3,4)
    const float* __restrict__ Wq,   // W_query (6,4)
    float* __restrict__ out)
{
    const int tid = threadIdx.x;
    const int r  = blockIdx.x * BSZ + tid;
    const int b  = r >> 16;
    const int n  = r & 65535;
    const int pi = n >> 8;
    const int pj = n & 255;

    float xv = 1.0f - (float)pj * (2.0f / 255.0f); if (pj == 255) xv = -1.0f;
    float yv = 1.0f - (float)pi * (2.0f / 255.0f); if (pi == 255) yv = -1.0f;
    float cx = xv / 4.2f;
    float cy = yv / 4.2f;

    const float* M = tm + b * 12;
    float ddx = M[0]*cx + M[1]*cy + M[2];
    float ddy = M[4]*cx + M[5]*cy + M[6];
    float ddz = M[8]*cx + M[9]*cy + M[10];
    float ox = M[3], oy = M[7], oz = M[11];

    // feat(d) = base + d*slope; pre-scaled by 0.5: sigmoid = 0.5*tanh(arg)+0.5
    float bh[4], sh[4];
    #pragma unroll
    for (int c = 0; c < 4; c++) {
        float w0 = Wq[c], w1 = Wq[4+c], w2 = Wq[8+c];
        float w3 = Wq[12+c], w4 = Wq[16+c], w5 = Wq[20+c];
        sh[c] = 0.5f * (ddx*w0 + ddy*w1 + ddz*w2);
        bh[c] = 0.5f * (ox*w0 + oy*w1 + oz*w2 + ddx*w3 + ddy*w4 + ddz*w5);
    }
    unsigned long long SH01, SH23, BH01, BH23;
    PACK2(SH01, sh[0], sh[1]);
    PACK2(SH23, sh[2], sh[3]);
    PACK2(BH01, bh[0], bh[1]);
    PACK2(BH23, bh[2], bh[3]);
    const float sh0 = sh[0], bh0 = bh[0];

    // ---- Pass 1: coarse march (no stores; cumsum recomputed later) ----
    float u1 = 0.5f, A0 = 0.f, A1 = 0.f, A2 = 0.f, cc1 = 0.f;
    {
        float dcur = 0.1f;
        #pragma unroll 16
        for (int p = 0; p < 64; p++) {
            float d  = (p == 63) ? 2.0f : dcur;
            unsigned long long D2, G01, G23;
            PACK2(D2, d, d);
            FMA2(G01, D2, SH01, BH01);
            FMA2(G23, D2, SH23, BH23);
            float g0, g1, g2, g3;
            UNPACK2(g0, g1, G01);
            UNPACK2(g2, g3, G23);
            float t0 = tanh_fast(g0);
            float t1 = tanh_fast(g1);
            float t2 = tanh_fast(g2);
            float t3 = tanh_fast(g3);
            float w  = fmaf(u1, t0, u1);
            u1 = fmaf(-0.5f, w, u1);
            A0 = fmaf(w, t1, A0);
            A1 = fmaf(w, t2, A1);
            A2 = fmaf(w, t3, A2);
            cc1 += w + 1e-5f;
            dcur += STEP;
        }
    }
    const float s  = cc1;                      // total of wpad
    // Sum(w) = 1 - T = 1 - 2*u1; a = 0.5*(A + Sum(w))
    const float h1 = 0.5f - u1;
    const float a0 = fmaf(0.5f, A0, h1);
    const float a1 = fmaf(0.5f, A1, h1);
    const float a2 = fmaf(0.5f, A2, h1);

    // ---- Pass 2+3 fused: inverse-CDF sampling feeding the merged march ----
    // searchsorted(cumsum(wpad)/s, u, 'right') == searchsorted(cumsum(wpad), u*s)
    // The coarse cumsum is REGENERATED via the identical t0-only recurrence
    // (bitwise-equal to pass 1's w sequence), so no shared-memory buffer.
    // Fine midpoints emerge sorted; consume each immediately, draining pending
    // coarse march samples first (coarse-first on ties == stable sort).
    float u3 = 0.5f, F0 = 0.f, F1 = 0.f, F2 = 0.f, accd = 0.f;
    {
        const float su = s * (1.0f / 64.0f);
        float u2 = 0.5f;                       // cumsum regeneration recurrence
        float cc = 0.0f;
        float cprev = 0.0f, prevbin = 0.0f, dprev = 0.1f;
        float us = 0.0f;                       // u_k * s, incremental
        float dcur = 0.1f;                     // CDF-bin depth walker
        float dc = 0.1f;                       // march coarse depth walker
        int k = 0, pc = 0;
        #pragma unroll 1
        for (int p = 0; p < 64; p++) {
            float d  = (p == 63) ? 2.0f : dcur;
            {   // regenerate w_p exactly as in pass 1
                float t0 = tanh_fast(fmaf(d, sh0, bh0));
                float w  = fmaf(u2, t0, u2);
                u2 = fmaf(-0.5f, w, u2);
                cc += w + 1e-5f;
            }
            while (k <= 64 && us < cc) {       // ind == p (side='right')
                float bin;
                if (p == 0) {
                    bin = 0.1f;
                } else {
                    float t = __fdividef(us - cprev, cc - cprev);
                    t = fminf(fmaxf(t, 0.0f), 1.0f);
                    bin = fmaf(t, d - dprev, dprev);
                }
                if (k > 0) {
                    float m = 0.5f * (prevbin + bin);  // fine midpoint (sorted)
                    DRAIN_COARSE(m);
                    SAMP(m);
                }
                prevbin = bin;
                k++;
                us += su;
            }
            cprev = cc;
            dprev = d;
            dcur += STEP;
        }
        while (k <= 64) {                      // ind == 64 -> depth[63] = FAR
            float bin = 2.0f;
            if (k > 0) {
                float m = 0.5f * (prevbin + bin);
                DRAIN_COARSE(m);
                SAMP(m);
            }
            prevbin = bin;
            k++;
        }
        DRAIN_COARSE(3.0e38f);                 // flush remaining coarse
    }
    const float fsum = 1.0f - 2.0f * u3;       // Sum(w) over merged march
    const float h3 = 0.5f - u3;
    const float f0 = fmaf(0.5f, F0, h3);
    const float f1 = fmaf(0.5f, F1, h3);
    const float f2 = fmaf(0.5f, F2, h3);
    float fop  = fminf(fsum, 1.0f);
    float rayd = accd + (1.0f - fop) * 2.0f;   // d_all.max() == FAR globally

    // ---- Outputs ----
    out[(3*b + 0) * HW + n] = a0;
    out[(3*b + 1) * HW + n] = a1;
    out[(3*b + 2) * HW + n] = a2;
    out[F_OFF + (3*b + 0) * HW + n] = f0;
    out[F_OFF + (3*b + 1) * HW + n] = f1;
    out[F_OFF + (3*b + 2) * HW + n] = f2;
    g_rayd[r] = rayd;

    // ---- block min/max partials (2 warps) ----
    float mn = rayd, mx = rayd;
    #pragma unroll
    for (int o = 16; o; o >>= 1) {
        mn = fminf(mn, __shfl_xor_sync(0xffffffffu, mn, o));
        mx = fmaxf(mx, __shfl_xor_sync(0xffffffffu, mx, o));
    }
    __shared__ float smn[2], smx[2];
    if ((tid & 31) == 0) { smn[tid >> 5] = mn; smx[tid >> 5] = mx; }
    __syncthreads();
    if (tid == 0) {
        g_pmin[blockIdx.x] = fminf(mn, smn[1]);
        g_pmax[blockIdx.x] = fmaxf(mx, smx[1]);
    }
}

// One-block global min/max over the 2048 partials; writes {min, 1/(max-min)}.
__global__ void __launch_bounds__(1024) nerf_reduce()
{
    const int t = threadIdx.x;
    float mn = fminf(g_pmin[t], g_pmin[t + 1024]);
    float mx = fmaxf(g_pmax[t], g_pmax[t + 1024]);
    #pragma unroll
    for (int o = 16; o; o >>= 1) {
        mn = fminf(mn, __shfl_xor_sync(0xffffffffu, mn, o));
        mx = fmaxf(mx, __shfl_xor_sync(0xffffffffu, mx, o));
    }
    __shared__ float smn[32], smx[32];
    if ((t & 31) == 0) { smn[t >> 5] = mn; smx[t >> 5] = mx; }
    __syncthreads();
    if (t < 32) {
        mn = smn[t];
        mx = smx[t];
        #pragma unroll
        for (int o = 16; o; o >>= 1) {
            mn = fminf(mn, __shfl_xor_sync(0xffffffffu, mn, o));
            mx = fmaxf(mx, __shfl_xor_sync(0xffffffffu, mx, o));
        }
        if (t == 0) { g_mm[0] = mn; g_mm[1] = 1.0f / (mx - mn); }
    }
}

// Vectorized normalize: 32768 threads x float4.
__global__ void __launch_bounds__(512) nerf_norm(float* __restrict__ out)
{
    const int i = blockIdx.x * 512 + threadIdx.x;
    const float mn = g_mm[0];
    const float sc = g_mm[1];
    float4 v = reinterpret_cast<const float4*>(g_rayd)[i];
    float4 o;
    o.x = (v.x - mn) * sc;
    o.y = (v.y - mn) * sc;
    o.z = (v.z - mn) * sc;
    o.w = (v.w - mn) * sc;
    reinterpret_cast<float4*>(out + D_OFF)[i] = o;
}

extern "C" void kernel_launch(void* const* d_in, const int* in_sizes, int n_in,
                              void* d_out, int out_size)
{
    const float* tm = (const float*)d_in[0];   // transform_matrix (2,3,4)
    const float* Wq = (const float*)d_in[1];   // W_query (6,4)
    float* out = (float*)d_out;

    nerf_main<<<NBLK, BSZ>>>(tm, Wq, out);
    nerf_reduce<<<1, 1024>>>();
    nerf_norm<<<NRAYS / 4 / 512, 512>>>(out);
}